// round 9
// baseline (speedup 1.0000x reference)
#include <cuda_runtime.h>
#include <cuda_bf16.h>

#define N_GENE 4762
#define N_CELL 847
#define D 256
#define E_MAX 200064
#define NSUB 16
#define TM 64
#define NBLK 148
#define NT1 1024
#define GT 512   // gemm threads

// ---------------- device scratch (zero-init at load; k_score cleanup restores) --
__device__ float g_norm_gsrc[N_GENE];
__device__ float g_norm_cdst[N_CELL];
__device__ float g_norm_csrc[N_CELL];
__device__ float g_norm_gdst[N_GENE];
__device__ int   g_subdeg_c[N_CELL * NSUB];
__device__ int   g_subdeg_g[N_GENE * NSUB];
__device__ int   g_subdeg_gsrc[N_GENE * NSUB];
__device__ int   g_subdeg_csrc[N_CELL * NSUB];
__device__ int   g_offs_c[N_CELL * NSUB + 1];
__device__ int   g_offs_g[N_GENE * NSUB + 1];
__device__ int   g_cursor_c[N_CELL * NSUB];
__device__ int   g_cursor_g[N_GENE * NSUB];
__device__ int   g_csr_g2c[E_MAX];
__device__ int   g_csr_c2g[E_MAX];
__device__ float g_agg_c[N_CELL * D];
__device__ float g_agg_g[N_GENE * D];
__device__ float g_sg[N_GENE];
__device__ float g_sc[N_CELL];
__device__ int   g_bsum[2 * NBLK];

// grid barrier (monotonic generation; valid across graph replays)
__device__ unsigned g_cnt = 0;
__device__ volatile unsigned g_gen = 0;

#define GSYNC() do {                                                          \
    ++ep;                                                                     \
    __syncthreads();                                                          \
    if (threadIdx.x == 0) {                                                   \
        __threadfence();                                                      \
        unsigned t = atomicAdd(&g_cnt, 1u);                                   \
        if ((t % NBLK) == NBLK - 1) { __threadfence(); g_gen = ep; }          \
        else { while ((int)(g_gen - ep) < 0) __nanosleep(64); }               \
        __threadfence();                                                      \
    }                                                                         \
    __syncthreads();                                                          \
} while (0)

// ---------------- f32x2 helpers ----------------
__device__ __forceinline__ unsigned long long pack2(float a) {
    unsigned long long r;
    asm("mov.b64 %0, {%1, %1};" : "=l"(r) : "f"(a));
    return r;
}
__device__ __forceinline__ void ffma2(unsigned long long& d, unsigned long long a,
                                      unsigned long long b) {
    asm("fma.rn.f32x2 %0, %1, %2, %3;" : "=l"(d) : "l"(a), "l"(b), "l"(d));
}
__device__ __forceinline__ void unpack2(unsigned long long v, float& lo, float& hi) {
    asm("mov.b64 {%0, %1}, %2;" : "=f"(lo), "=f"(hi) : "l"(v));
}

// ---------------- launch 1: cooperative deg + scan + norms ----------------
__device__ __forceinline__ int coop_scan_chunk(const int* __restrict__ deg,
                                               int* __restrict__ offs,
                                               int L, int bid, int tid, int* ws) {
    int chunk = (L + NBLK - 1) / NBLK;     // <= 515 (< NT1)
    int start = bid * chunk;
    int i = start + tid;
    int v = (tid < chunk && i < L) ? deg[i] : 0;

    int lane = tid & 31, w = tid >> 5;
    int incl = v;
#pragma unroll
    for (int o = 1; o < 32; o <<= 1) {
        int t = __shfl_up_sync(0xffffffffu, incl, o);
        if (lane >= o) incl += t;
    }
    if (lane == 31) ws[w] = incl;
    __syncthreads();
    if (w == 0) {
        int t0 = ws[lane];
        int inc2 = t0;
#pragma unroll
        for (int o = 1; o < 32; o <<= 1) {
            int t = __shfl_up_sync(0xffffffffu, inc2, o);
            if (lane >= o) inc2 += t;
        }
        ws[lane] = inc2 - t0;
        if (lane == 31) ws[32] = inc2;
    }
    __syncthreads();
    int tot = ws[32];
    if (tid < chunk && i < L) offs[i] = ws[w] + (incl - v);
    __syncthreads();
    return tot;
}

__device__ __forceinline__ void coop_add_base(int* __restrict__ offs, int L,
                                              int slot, int bid, int tid,
                                              int mytot, int* sred) {
    int chunk = (L + NBLK - 1) / NBLK;
    int start = bid * chunk;
    int end = min(L, start + chunk);
    if (tid < 32) {
        int s = 0;
        for (int k = tid; k < bid; k += 32) s += g_bsum[slot * NBLK + k];
#pragma unroll
        for (int o = 16; o; o >>= 1) s += __shfl_xor_sync(0xffffffffu, s, o);
        if (tid == 0) sred[0] = s;
    }
    __syncthreads();
    int base = sred[0];
    int i = start + tid;
    if (tid < chunk && i < end) offs[i] += base;
    if (tid == 0 && end == L && start < L) offs[L] = base + mytot;
    __syncthreads();
}

__global__ void __launch_bounds__(NT1, 1)
k_pre(const int* __restrict__ s1, const int* __restrict__ d1, int E1,
      const int* __restrict__ s2, const int* __restrict__ d2, int E2) {
    __shared__ int ws[40];
    int bid = blockIdx.x, tid = threadIdx.x;
    unsigned ep = g_gen;

    for (int i = bid * NT1 + tid; i < E1 + E2; i += NBLK * NT1) {
        if (i < E1) {
            int sub = i & (NSUB - 1);
            atomicAdd(&g_subdeg_gsrc[s1[i] * NSUB + sub], 1);
            atomicAdd(&g_subdeg_c[d1[i] * NSUB + sub], 1);
        } else {
            int j = i - E1;
            int sub = j & (NSUB - 1);
            atomicAdd(&g_subdeg_csrc[s2[j] * NSUB + sub], 1);
            atomicAdd(&g_subdeg_g[d2[j] * NSUB + sub], 1);
        }
    }
    GSYNC();

    int tot_c = coop_scan_chunk(g_subdeg_c, g_offs_c, N_CELL * NSUB, bid, tid, ws);
    int tot_g = coop_scan_chunk(g_subdeg_g, g_offs_g, N_GENE * NSUB, bid, tid, ws);
    if (tid == 0) { g_bsum[bid] = tot_c; g_bsum[NBLK + bid] = tot_g; }

    for (int i = bid * NT1 + tid; i < N_CELL; i += NBLK * NT1) {
        int a0 = 0, a1 = 0;
#pragma unroll
        for (int k = 0; k < NSUB; k++) {
            a0 += g_subdeg_c[i * NSUB + k];
            a1 += g_subdeg_csrc[i * NSUB + k];
        }
        g_norm_cdst[i] = rsqrtf(fmaxf((float)a0, 1.0f));
        g_norm_csrc[i] = rsqrtf(fmaxf((float)a1, 1.0f));
    }
    for (int i = bid * NT1 + tid; i < N_GENE; i += NBLK * NT1) {
        int a0 = 0, a1 = 0;
#pragma unroll
        for (int k = 0; k < NSUB; k++) {
            a0 += g_subdeg_g[i * NSUB + k];
            a1 += g_subdeg_gsrc[i * NSUB + k];
        }
        g_norm_gdst[i] = rsqrtf(fmaxf((float)a0, 1.0f));
        g_norm_gsrc[i] = rsqrtf(fmaxf((float)a1, 1.0f));
    }
    GSYNC();

    coop_add_base(g_offs_c, N_CELL * NSUB, 0, bid, tid, tot_c, ws);
    coop_add_base(g_offs_g, N_GENE * NSUB, 1, bid, tid, tot_g, ws);
}

// ---------------- launch 2: CSR fill ----------------
__global__ void k_fill(const int* __restrict__ s1, const int* __restrict__ d1, int E1,
                       const int* __restrict__ s2, const int* __restrict__ d2, int E2) {
    int i = blockIdx.x * blockDim.x + threadIdx.x;
    if (i < E1) {
        int s = s1[i], d = d1[i];
        int bkt = d * NSUB + (i & (NSUB - 1));
        int p = atomicAdd(&g_cursor_c[bkt], 1);
        g_csr_g2c[g_offs_c[bkt] + p] = s;
    } else if (i < E1 + E2) {
        int j = i - E1;
        int s = s2[j], d = d2[j];
        int bkt = d * NSUB + (j & (NSUB - 1));
        int p = atomicAdd(&g_cursor_g[bkt], 1);
        g_csr_c2g[g_offs_g[bkt] + p] = s;
    }
}

// ---------------- launch 3: aggregation (at LTS roofline) ----------
__global__ void k_agg(const float* __restrict__ gene_emb,
                      const float* __restrict__ cell_emb) {
    int b = blockIdx.x, tid = threadIdx.x;
    const float* emb; const int* csr; const float* nsrc;
    float* outp; float nd; int beg, end;
    if (b < N_CELL) {
        emb = gene_emb; csr = g_csr_g2c; nsrc = g_norm_gsrc;
        beg = g_offs_c[b * NSUB]; end = g_offs_c[b * NSUB + NSUB];
        nd = g_norm_cdst[b]; outp = g_agg_c + b * D;
    } else {
        int r = b - N_CELL;
        emb = cell_emb; csr = g_csr_c2g; nsrc = g_norm_csrc;
        beg = g_offs_g[r * NSUB]; end = g_offs_g[r * NSUB + NSUB];
        nd = g_norm_gdst[r]; outp = g_agg_g + r * D;
    }

    __shared__ int   sidx[256];
    __shared__ float snrm[256];
    float acc = 0.0f;

    for (int base = beg; base < end; base += 256) {
        int m = end - base; if (m > 256) m = 256;
        __syncthreads();
        if (tid < m) {
            int idx = csr[base + tid];
            sidx[tid] = idx;
            snrm[tid] = nsrc[idx];
        }
        __syncthreads();
        int j = 0;
        for (; j + 16 <= m; j += 16) {
            float f[16];
#pragma unroll
            for (int u = 0; u < 16; u++) f[u] = emb[sidx[j + u] * D + tid];
#pragma unroll
            for (int u = 0; u < 16; u++) acc = fmaf(f[u], snrm[j + u], acc);
        }
        for (; j + 4 <= m; j += 4) {
            float f0 = emb[sidx[j + 0] * D + tid];
            float f1 = emb[sidx[j + 1] * D + tid];
            float f2 = emb[sidx[j + 2] * D + tid];
            float f3 = emb[sidx[j + 3] * D + tid];
            acc = fmaf(f0, snrm[j + 0], acc);
            acc = fmaf(f1, snrm[j + 1], acc);
            acc = fmaf(f2, snrm[j + 2], acc);
            acc = fmaf(f3, snrm[j + 3], acc);
        }
        for (; j < m; j++) acc = fmaf(emb[sidx[j] * D + tid], snrm[j], acc);
    }

    outp[tid] = acc * nd;
}

// ---------------- launch 4 (PROFILED SLOT): GEMM, 512 threads ----------------
// 64 rows x 256 cols per block; thread = 4 rows x 8 cols; 16 warps/SM.
__global__ void __launch_bounds__(GT, 1)
k_gemm(const float* __restrict__ W_g2c, const float* __restrict__ b_g2c,
       const float* __restrict__ W_c2g, const float* __restrict__ b_c2g,
       const float* __restrict__ Wp,
       float* __restrict__ h_cell, float* __restrict__ h_gene) {
    const int CB = (N_CELL + TM - 1) / TM;
    int blk = blockIdx.x, tid = threadIdx.x;

    const float* A; const float* W; const float* bias; float* O; float* sv;
    int n, row0, wpoff;
    if (blk < CB) {
        A = g_agg_c; W = W_g2c; bias = b_g2c; O = h_cell; sv = g_sc;
        n = N_CELL; row0 = blk * TM; wpoff = 256;
    } else {
        A = g_agg_g; W = W_c2g; bias = b_c2g; O = h_gene; sv = g_sg;
        n = N_GENE; row0 = (blk - CB) * TM; wpoff = 0;
    }

    __shared__ float sA[32][TM];     // [k][row] 8KB
    __shared__ float sW[32][256];    // [k][col] 32KB

    int tx = tid & 31;       // cols tx*8..+8
    int ty = tid >> 5;       // warp 0..15, rows ty*4..+4

    unsigned long long acc[4][4];
#pragma unroll
    for (int j = 0; j < 4; j++)
#pragma unroll
        for (int c = 0; c < 4; c++) acc[j][c] = 0ull;

    // staging roles (512 threads)
    int a_row  = tid >> 3;           // 0..63
    int a_kseg = (tid & 7) * 4;      // 0,4,...,28
    int w_k    = tid >> 4;           // 0..31
    int w_col  = (tid & 15) * 16;    // 0..240

    for (int kc = 0; kc < 256; kc += 32) {
        {
            int gr = row0 + a_row;
            float4 v0 = (gr < n) ? *(const float4*)&A[gr * D + kc + a_kseg]
                                 : make_float4(0.f, 0.f, 0.f, 0.f);
            sA[a_kseg + 0][a_row] = v0.x;
            sA[a_kseg + 1][a_row] = v0.y;
            sA[a_kseg + 2][a_row] = v0.z;
            sA[a_kseg + 3][a_row] = v0.w;
        }
        {
            const float4* src = (const float4*)&W[(kc + w_k) * D + w_col];
            float4* dst = (float4*)&sW[w_k][w_col];
#pragma unroll
            for (int i = 0; i < 4; i++) dst[i] = src[i];
        }
        __syncthreads();

#pragma unroll
        for (int k = 0; k < 32; k++) {
            const unsigned long long* wp2 =
                (const unsigned long long*)&sW[k][tx * 8];
            unsigned long long w0 = wp2[0], w1 = wp2[1], w2 = wp2[2], w3 = wp2[3];
            float4 av = *(const float4*)&sA[k][ty * 4];
            float ar[4] = {av.x, av.y, av.z, av.w};
#pragma unroll
            for (int j = 0; j < 4; j++) {
                unsigned long long a2 = pack2(ar[j]);
                ffma2(acc[j][0], a2, w0);
                ffma2(acc[j][1], a2, w1);
                ffma2(acc[j][2], a2, w2);
                ffma2(acc[j][3], a2, w3);
            }
        }
        __syncthreads();
    }

    float bv[8], wv[8];
#pragma unroll
    for (int i = 0; i < 8; i++) {
        bv[i] = bias[tx * 8 + i];
        wv[i] = Wp[wpoff + tx * 8 + i];
    }

#pragma unroll
    for (int j = 0; j < 4; j++) {
        int gr = row0 + ty * 4 + j;
        float h[8];
#pragma unroll
        for (int c = 0; c < 4; c++) {
            float lo, hi;
            unpack2(acc[j][c], lo, hi);
            h[2 * c]     = fmaxf(lo + bv[2 * c], 0.0f);
            h[2 * c + 1] = fmaxf(hi + bv[2 * c + 1], 0.0f);
        }
        float p = 0.0f;
        if (gr < n) {
            float4* o0 = (float4*)&O[gr * D + tx * 8];
            o0[0] = make_float4(h[0], h[1], h[2], h[3]);
            o0[1] = make_float4(h[4], h[5], h[6], h[7]);
#pragma unroll
            for (int i = 0; i < 8; i++) p = fmaf(h[i], wv[i], p);
        }
#pragma unroll
        for (int o = 16; o; o >>= 1) p += __shfl_xor_sync(0xffffffffu, p, o);
        if (tx == 0 && gr < n) sv[gr] = p;
    }
}

// ---------------- launch 5: scores + cleanup ----------------
__global__ void k_score(const int* __restrict__ dsrc, const int* __restrict__ ddst,
                        const float* __restrict__ bp, float* __restrict__ out, int E) {
    int i = blockIdx.x * blockDim.x + threadIdx.x;
    if (i < E) out[i] = g_sg[dsrc[i]] + g_sc[ddst[i]] + bp[0];

    if (i < N_CELL * NSUB) { g_subdeg_c[i] = 0; g_subdeg_csrc[i] = 0; g_cursor_c[i] = 0; }
    if (i < N_GENE * NSUB) { g_subdeg_g[i] = 0; g_subdeg_gsrc[i] = 0; g_cursor_g[i] = 0; }
}

// ---------------- launch ----------------
extern "C" void kernel_launch(void* const* d_in, const int* in_sizes, int n_in,
                              void* d_out, int out_size) {
    const float* gene_emb = (const float*)d_in[0];
    const float* cell_emb = (const float*)d_in[1];
    const float* W_g2c    = (const float*)d_in[2];
    const float* b_g2c    = (const float*)d_in[3];
    const float* W_c2g    = (const float*)d_in[4];
    const float* b_c2g    = (const float*)d_in[5];
    const float* Wp       = (const float*)d_in[6];
    const float* bp       = (const float*)d_in[7];
    const int* g2c_src    = (const int*)d_in[8];
    const int* g2c_dst    = (const int*)d_in[9];
    const int* c2g_src    = (const int*)d_in[10];
    const int* c2g_dst    = (const int*)d_in[11];
    const int* dec_src    = (const int*)d_in[12];
    const int* dec_dst    = (const int*)d_in[13];

    int E1 = in_sizes[8];
    int E2 = in_sizes[10];
    int E3 = in_sizes[12];

    float* out    = (float*)d_out;
    float* score  = out;
    float* h_gene = out + E3;
    float* h_cell = out + E3 + (long)N_GENE * D;

    k_pre<<<NBLK, NT1>>>(g2c_src, g2c_dst, E1, c2g_src, c2g_dst, E2);
    k_fill<<<(E1 + E2 + 255) / 256, 256>>>(g2c_src, g2c_dst, E1, c2g_src, c2g_dst, E2);
    k_agg<<<N_CELL + N_GENE, 256>>>(gene_emb, cell_emb);

    const int CB = (N_CELL + TM - 1) / TM;
    const int GB = (N_GENE + TM - 1) / TM;
    k_gemm<<<CB + GB, GT>>>(W_g2c, b_g2c, W_c2g, b_c2g, Wp, h_cell, h_gene);

    k_score<<<(E3 + 255) / 256, 256>>>(dec_src, dec_dst, bp, score, E3);
}

// round 10
// speedup vs baseline: 1.1663x; 1.1663x over previous
#include <cuda_runtime.h>
#include <cuda_bf16.h>

#define N_GENE 4762
#define N_CELL 847
#define D 256
#define E_MAX 200064
#define NSUB 8
#define TM 48
#define NBLK 148
#define NT1 1024

// ---------------- device scratch (zero-init at load; k_score cleanup restores) --
__device__ float g_norm_gsrc[N_GENE];
__device__ float g_norm_cdst[N_CELL];
__device__ float g_norm_csrc[N_CELL];
__device__ float g_norm_gdst[N_GENE];
__device__ int   g_subdeg_c[N_CELL * NSUB];
__device__ int   g_subdeg_g[N_GENE * NSUB];
__device__ int   g_subdeg_gsrc[N_GENE * NSUB];
__device__ int   g_subdeg_csrc[N_CELL * NSUB];
__device__ int   g_offs_c[N_CELL * NSUB + 1];
__device__ int   g_offs_g[N_GENE * NSUB + 1];
__device__ int   g_cursor_c[N_CELL * NSUB];
__device__ int   g_cursor_g[N_GENE * NSUB];
__device__ int   g_csr_g2c[E_MAX];
__device__ int   g_csr_c2g[E_MAX];
__device__ float g_agg_c[N_CELL * D];
__device__ float g_agg_g[N_GENE * D];
__device__ float g_sg[N_GENE];
__device__ float g_sc[N_CELL];
__device__ int   g_bsum[2 * NBLK];

// grid barrier (monotonic generation; valid across graph replays)
__device__ unsigned g_cnt = 0;
__device__ volatile unsigned g_gen = 0;

#define GSYNC() do {                                                          \
    ++ep;                                                                     \
    __syncthreads();                                                          \
    if (threadIdx.x == 0) {                                                   \
        __threadfence();                                                      \
        unsigned t = atomicAdd(&g_cnt, 1u);                                   \
        if ((t % NBLK) == NBLK - 1) { __threadfence(); g_gen = ep; }          \
        else { while ((int)(g_gen - ep) < 0) __nanosleep(64); }               \
        __threadfence();                                                      \
    }                                                                         \
    __syncthreads();                                                          \
} while (0)

// ---------------- f32x2 helpers ----------------
__device__ __forceinline__ unsigned long long pack2(float a) {
    unsigned long long r;
    asm("mov.b64 %0, {%1, %1};" : "=l"(r) : "f"(a));
    return r;
}
__device__ __forceinline__ void ffma2(unsigned long long& d, unsigned long long a,
                                      unsigned long long b) {
    asm("fma.rn.f32x2 %0, %1, %2, %3;" : "=l"(d) : "l"(a), "l"(b), "l"(d));
}
__device__ __forceinline__ void unpack2(unsigned long long v, float& lo, float& hi) {
    asm("mov.b64 {%0, %1}, %2;" : "=f"(lo), "=f"(hi) : "l"(v));
}

// ---------------- launch 1: cooperative deg + scan + norms ----------------
__device__ __forceinline__ int coop_scan_chunk(const int* __restrict__ deg,
                                               int* __restrict__ offs,
                                               int L, int bid, int tid, int* ws) {
    int chunk = (L + NBLK - 1) / NBLK;
    int start = bid * chunk;
    int i = start + tid;
    int v = (tid < chunk && i < L) ? deg[i] : 0;

    int lane = tid & 31, w = tid >> 5;
    int incl = v;
#pragma unroll
    for (int o = 1; o < 32; o <<= 1) {
        int t = __shfl_up_sync(0xffffffffu, incl, o);
        if (lane >= o) incl += t;
    }
    if (lane == 31) ws[w] = incl;
    __syncthreads();
    if (w == 0) {
        int t0 = ws[lane];
        int inc2 = t0;
#pragma unroll
        for (int o = 1; o < 32; o <<= 1) {
            int t = __shfl_up_sync(0xffffffffu, inc2, o);
            if (lane >= o) inc2 += t;
        }
        ws[lane] = inc2 - t0;
        if (lane == 31) ws[32] = inc2;
    }
    __syncthreads();
    int tot = ws[32];
    if (tid < chunk && i < L) offs[i] = ws[w] + (incl - v);
    __syncthreads();
    return tot;
}

__device__ __forceinline__ void coop_add_base(int* __restrict__ offs, int L,
                                              int slot, int bid, int tid,
                                              int mytot, int* sred) {
    int chunk = (L + NBLK - 1) / NBLK;
    int start = bid * chunk;
    int end = min(L, start + chunk);
    if (tid < 32) {
        int s = 0;
        for (int k = tid; k < bid; k += 32) s += g_bsum[slot * NBLK + k];
#pragma unroll
        for (int o = 16; o; o >>= 1) s += __shfl_xor_sync(0xffffffffu, s, o);
        if (tid == 0) sred[0] = s;
    }
    __syncthreads();
    int base = sred[0];
    int i = start + tid;
    if (tid < chunk && i < end) offs[i] += base;
    if (tid == 0 && end == L && start < L) offs[L] = base + mytot;
    __syncthreads();
}

__global__ void __launch_bounds__(NT1, 1)
k_pre(const int* __restrict__ s1, const int* __restrict__ d1, int E1,
      const int* __restrict__ s2, const int* __restrict__ d2, int E2) {
    __shared__ int ws[40];
    int bid = blockIdx.x, tid = threadIdx.x;
    unsigned ep = g_gen;

    for (int i = bid * NT1 + tid; i < E1 + E2; i += NBLK * NT1) {
        if (i < E1) {
            int sub = i & (NSUB - 1);
            atomicAdd(&g_subdeg_gsrc[s1[i] * NSUB + sub], 1);
            atomicAdd(&g_subdeg_c[d1[i] * NSUB + sub], 1);
        } else {
            int j = i - E1;
            int sub = j & (NSUB - 1);
            atomicAdd(&g_subdeg_csrc[s2[j] * NSUB + sub], 1);
            atomicAdd(&g_subdeg_g[d2[j] * NSUB + sub], 1);
        }
    }
    GSYNC();

    int tot_c = coop_scan_chunk(g_subdeg_c, g_offs_c, N_CELL * NSUB, bid, tid, ws);
    int tot_g = coop_scan_chunk(g_subdeg_g, g_offs_g, N_GENE * NSUB, bid, tid, ws);
    if (tid == 0) { g_bsum[bid] = tot_c; g_bsum[NBLK + bid] = tot_g; }

    for (int i = bid * NT1 + tid; i < N_CELL; i += NBLK * NT1) {
        int a0 = 0, a1 = 0;
#pragma unroll
        for (int k = 0; k < NSUB; k++) {
            a0 += g_subdeg_c[i * NSUB + k];
            a1 += g_subdeg_csrc[i * NSUB + k];
        }
        g_norm_cdst[i] = rsqrtf(fmaxf((float)a0, 1.0f));
        g_norm_csrc[i] = rsqrtf(fmaxf((float)a1, 1.0f));
    }
    for (int i = bid * NT1 + tid; i < N_GENE; i += NBLK * NT1) {
        int a0 = 0, a1 = 0;
#pragma unroll
        for (int k = 0; k < NSUB; k++) {
            a0 += g_subdeg_g[i * NSUB + k];
            a1 += g_subdeg_gsrc[i * NSUB + k];
        }
        g_norm_gdst[i] = rsqrtf(fmaxf((float)a0, 1.0f));
        g_norm_gsrc[i] = rsqrtf(fmaxf((float)a1, 1.0f));
    }
    GSYNC();

    coop_add_base(g_offs_c, N_CELL * NSUB, 0, bid, tid, tot_c, ws);
    coop_add_base(g_offs_g, N_GENE * NSUB, 1, bid, tid, tot_g, ws);
}

// ---------------- launch 2: CSR fill ----------------
__global__ void k_fill(const int* __restrict__ s1, const int* __restrict__ d1, int E1,
                       const int* __restrict__ s2, const int* __restrict__ d2, int E2) {
    int i = blockIdx.x * blockDim.x + threadIdx.x;
    if (i < E1) {
        int s = s1[i], d = d1[i];
        int bkt = d * NSUB + (i & (NSUB - 1));
        int p = atomicAdd(&g_cursor_c[bkt], 1);
        g_csr_g2c[g_offs_c[bkt] + p] = s;
    } else if (i < E1 + E2) {
        int j = i - E1;
        int s = s2[j], d = d2[j];
        int bkt = d * NSUB + (j & (NSUB - 1));
        int p = atomicAdd(&g_cursor_g[bkt], 1);
        g_csr_c2g[g_offs_g[bkt] + p] = s;
    }
}

// ---------------- launch 3: aggregation (at LTS roofline) ----------
__global__ void k_agg(const float* __restrict__ gene_emb,
                      const float* __restrict__ cell_emb) {
    int b = blockIdx.x, tid = threadIdx.x;
    const float* emb; const int* csr; const float* nsrc;
    float* outp; float nd; int beg, end;
    if (b < N_CELL) {
        emb = gene_emb; csr = g_csr_g2c; nsrc = g_norm_gsrc;
        beg = g_offs_c[b * NSUB]; end = g_offs_c[b * NSUB + NSUB];
        nd = g_norm_cdst[b]; outp = g_agg_c + b * D;
    } else {
        int r = b - N_CELL;
        emb = cell_emb; csr = g_csr_c2g; nsrc = g_norm_csrc;
        beg = g_offs_g[r * NSUB]; end = g_offs_g[r * NSUB + NSUB];
        nd = g_norm_gdst[r]; outp = g_agg_g + r * D;
    }

    __shared__ int   sidx[256];
    __shared__ float snrm[256];
    float acc = 0.0f;

    for (int base = beg; base < end; base += 256) {
        int m = end - base; if (m > 256) m = 256;
        __syncthreads();
        if (tid < m) {
            int idx = csr[base + tid];
            sidx[tid] = idx;
            snrm[tid] = nsrc[idx];
        }
        __syncthreads();
        int j = 0;
        for (; j + 16 <= m; j += 16) {
            float f[16];
#pragma unroll
            for (int u = 0; u < 16; u++) f[u] = emb[sidx[j + u] * D + tid];
#pragma unroll
            for (int u = 0; u < 16; u++) acc = fmaf(f[u], snrm[j + u], acc);
        }
        for (; j + 4 <= m; j += 4) {
            float f0 = emb[sidx[j + 0] * D + tid];
            float f1 = emb[sidx[j + 1] * D + tid];
            float f2 = emb[sidx[j + 2] * D + tid];
            float f3 = emb[sidx[j + 3] * D + tid];
            acc = fmaf(f0, snrm[j + 0], acc);
            acc = fmaf(f1, snrm[j + 1], acc);
            acc = fmaf(f2, snrm[j + 2], acc);
            acc = fmaf(f3, snrm[j + 3], acc);
        }
        for (; j < m; j++) acc = fmaf(emb[sidx[j] * D + tid], snrm[j], acc);
    }

    outp[tid] = acc * nd;
}

// ---------------- launch 4 (PROFILED SLOT): GEMM, TM=48, 118 blocks --------
// 48 rows x 256 cols per block; 256 threads; thread = 6 rows x 8 cols.
__global__ void __launch_bounds__(256, 1)
k_gemm(const float* __restrict__ W_g2c, const float* __restrict__ b_g2c,
       const float* __restrict__ W_c2g, const float* __restrict__ b_c2g,
       const float* __restrict__ Wp,
       float* __restrict__ h_cell, float* __restrict__ h_gene) {
    const int CB = (N_CELL + TM - 1) / TM;   // 18
    int blk = blockIdx.x, tid = threadIdx.x;

    const float* A; const float* W; const float* bias; float* O; float* sv;
    int n, row0, wpoff;
    if (blk < CB) {
        A = g_agg_c; W = W_g2c; bias = b_g2c; O = h_cell; sv = g_sc;
        n = N_CELL; row0 = blk * TM; wpoff = 256;
    } else {
        A = g_agg_g; W = W_c2g; bias = b_c2g; O = h_gene; sv = g_sg;
        n = N_GENE; row0 = (blk - CB) * TM; wpoff = 0;
    }

    __shared__ float sA[32][TM];     // [k][row] 6KB
    __shared__ float sW[32][256];    // [k][col] 32KB

    int tx = tid & 31;       // cols tx*8..+8
    int ty = tid >> 5;       // warp 0..7, rows ty*6..+6

    unsigned long long acc[6][4];
#pragma unroll
    for (int j = 0; j < 6; j++)
#pragma unroll
        for (int c = 0; c < 4; c++) acc[j][c] = 0ull;

    // staging: A uses threads 0..191 (4 per row, 8 floats each); W all 256.
    int a_row  = tid >> 2;           // 0..63 (use <48)
    int a_kseg = (tid & 3) * 8;
    int w_k    = tid >> 3;           // 0..31
    int w_col  = (tid & 7) * 32;

    for (int kc = 0; kc < 256; kc += 32) {
        if (a_row < TM) {
            int gr = row0 + a_row;
            float4 v0, v1;
            if (gr < n) {
                v0 = *(const float4*)&A[gr * D + kc + a_kseg];
                v1 = *(const float4*)&A[gr * D + kc + a_kseg + 4];
            } else {
                v0 = make_float4(0.f, 0.f, 0.f, 0.f);
                v1 = v0;
            }
            sA[a_kseg + 0][a_row] = v0.x; sA[a_kseg + 1][a_row] = v0.y;
            sA[a_kseg + 2][a_row] = v0.z; sA[a_kseg + 3][a_row] = v0.w;
            sA[a_kseg + 4][a_row] = v1.x; sA[a_kseg + 5][a_row] = v1.y;
            sA[a_kseg + 6][a_row] = v1.z; sA[a_kseg + 7][a_row] = v1.w;
        }
        {
            const float4* src = (const float4*)&W[(kc + w_k) * D + w_col];
            float4* dst = (float4*)&sW[w_k][w_col];
#pragma unroll
            for (int i = 0; i < 8; i++) dst[i] = src[i];
        }
        __syncthreads();

#pragma unroll
        for (int k = 0; k < 32; k++) {
            // w: 8 cols = 2x LDS.128, reinterpret as 4 ull pairs
            ulonglong2 wa = *(const ulonglong2*)&sW[k][tx * 8];
            ulonglong2 wb = *(const ulonglong2*)&sW[k][tx * 8 + 4];
            // a: 6 rows = 3x LDS.64 (8B-aligned)
            float2 a01 = *(const float2*)&sA[k][ty * 6];
            float2 a23 = *(const float2*)&sA[k][ty * 6 + 2];
            float2 a45 = *(const float2*)&sA[k][ty * 6 + 4];
            float ar[6] = {a01.x, a01.y, a23.x, a23.y, a45.x, a45.y};
#pragma unroll
            for (int j = 0; j < 6; j++) {
                unsigned long long a2 = pack2(ar[j]);
                ffma2(acc[j][0], a2, wa.x);
                ffma2(acc[j][1], a2, wa.y);
                ffma2(acc[j][2], a2, wb.x);
                ffma2(acc[j][3], a2, wb.y);
            }
        }
        __syncthreads();
    }

    float bv[8], wv[8];
#pragma unroll
    for (int i = 0; i < 8; i++) {
        bv[i] = bias[tx * 8 + i];
        wv[i] = Wp[wpoff + tx * 8 + i];
    }

#pragma unroll
    for (int j = 0; j < 6; j++) {
        int gr = row0 + ty * 6 + j;
        float h[8];
#pragma unroll
        for (int c = 0; c < 4; c++) {
            float lo, hi;
            unpack2(acc[j][c], lo, hi);
            h[2 * c]     = fmaxf(lo + bv[2 * c], 0.0f);
            h[2 * c + 1] = fmaxf(hi + bv[2 * c + 1], 0.0f);
        }
        float p = 0.0f;
        if (gr < n) {
            float4* o0 = (float4*)&O[gr * D + tx * 8];
            o0[0] = make_float4(h[0], h[1], h[2], h[3]);
            o0[1] = make_float4(h[4], h[5], h[6], h[7]);
#pragma unroll
            for (int i = 0; i < 8; i++) p = fmaf(h[i], wv[i], p);
        }
#pragma unroll
        for (int o = 16; o; o >>= 1) p += __shfl_xor_sync(0xffffffffu, p, o);
        if (tx == 0 && gr < n) sv[gr] = p;
    }
}

// ---------------- launch 5: scores + cleanup ----------------
__global__ void k_score(const int* __restrict__ dsrc, const int* __restrict__ ddst,
                        const float* __restrict__ bp, float* __restrict__ out, int E) {
    int i = blockIdx.x * blockDim.x + threadIdx.x;
    if (i < E) out[i] = g_sg[dsrc[i]] + g_sc[ddst[i]] + bp[0];

    if (i < N_CELL * NSUB) { g_subdeg_c[i] = 0; g_subdeg_csrc[i] = 0; g_cursor_c[i] = 0; }
    if (i < N_GENE * NSUB) { g_subdeg_g[i] = 0; g_subdeg_gsrc[i] = 0; g_cursor_g[i] = 0; }
}

// ---------------- launch ----------------
extern "C" void kernel_launch(void* const* d_in, const int* in_sizes, int n_in,
                              void* d_out, int out_size) {
    const float* gene_emb = (const float*)d_in[0];
    const float* cell_emb = (const float*)d_in[1];
    const float* W_g2c    = (const float*)d_in[2];
    const float* b_g2c    = (const float*)d_in[3];
    const float* W_c2g    = (const float*)d_in[4];
    const float* b_c2g    = (const float*)d_in[5];
    const float* Wp       = (const float*)d_in[6];
    const float* bp       = (const float*)d_in[7];
    const int* g2c_src    = (const int*)d_in[8];
    const int* g2c_dst    = (const int*)d_in[9];
    const int* c2g_src    = (const int*)d_in[10];
    const int* c2g_dst    = (const int*)d_in[11];
    const int* dec_src    = (const int*)d_in[12];
    const int* dec_dst    = (const int*)d_in[13];

    int E1 = in_sizes[8];
    int E2 = in_sizes[10];
    int E3 = in_sizes[12];

    float* out    = (float*)d_out;
    float* score  = out;
    float* h_gene = out + E3;
    float* h_cell = out + E3 + (long)N_GENE * D;

    k_pre<<<NBLK, NT1>>>(g2c_src, g2c_dst, E1, c2g_src, c2g_dst, E2);
    k_fill<<<(E1 + E2 + 255) / 256, 256>>>(g2c_src, g2c_dst, E1, c2g_src, c2g_dst, E2);
    k_agg<<<N_CELL + N_GENE, 256>>>(gene_emb, cell_emb);

    const int CB = (N_CELL + TM - 1) / TM;
    const int GB = (N_GENE + TM - 1) / TM;
    k_gemm<<<CB + GB, 256>>>(W_g2c, b_g2c, W_c2g, b_c2g, Wp, h_cell, h_gene);

    k_score<<<(E3 + 255) / 256, 256>>>(dec_src, dec_dst, bp, score, E3);
}